// round 13
// baseline (speedup 1.0000x reference)
#include <cuda_runtime.h>
#include <cuda_bf16.h>
#include <cstdint>

// ---------------------------------------------------------------- constants
#define B_      8
#define T_      2048
#define C_      1024
#define G_      2
#define E_      320
#define GE_     640
#define D_      256
#define M_TOT   16384
#define NROWS   16
#define ROW_SPAN 655360u
#define OUT_ELEMS (B_*T_*G_*D_)          // 8,388,608
#define LOGITS_N ((size_t)M_TOT * GE_)   // 10,485,760

#define BM 128
#define BN 64
#define BK 32
#define PITCH 40            // bf16 per smem row (32 data + 8 pad) -> 80B
#define NCHUNK (C_/BK)      // 32
#define NSTAGE 4
#define A_ELE (BM * PITCH)               // 5120 bf16
#define B_ELE (BN * PITCH)               // 2560 bf16
#define STAGE_ELE (A_ELE + B_ELE)        // 7680
#define STAGE_BYTES (STAGE_ELE * 2)      // 15360
#define SMEM_BYTES (NSTAGE * STAGE_BYTES)  // 61440 -> 3 CTAs/SM
#define DELTA 4.0f
#define CAND_CAP 65536
#define EXACT_BLOCKS 256

// ---------------------------------------------------------------- scratch
__device__ unsigned long long g_best[NROWS];
__device__ int                g_cand_count;
__device__ unsigned int       g_done;
__device__ unsigned int       g_cand[CAND_CAP];
__device__ __align__(16) __nv_bfloat16 g_Xh[(size_t)M_TOT * C_];
__device__ __align__(16) __nv_bfloat16 g_Wh[(size_t)GE_ * C_];

// ---------------------------------------------------------------- helpers
__device__ __forceinline__ unsigned int float_to_ordered(float f) {
    unsigned int u = __float_as_uint(f);
    return (u & 0x80000000u) ? ~u : (u | 0x80000000u);
}
__device__ __forceinline__ uint32_t smem_u32(const void* p) {
    uint32_t a;
    asm("{ .reg .u64 t; cvta.to.shared.u64 t, %1; cvt.u32.u64 %0, t; }"
        : "=r"(a) : "l"(p));
    return a;
}
__device__ __forceinline__ void cp16(void* sptr, const void* gptr) {
    uint32_t s = smem_u32(sptr);
    asm volatile("cp.async.cg.shared.global [%0], [%1], 16;"
                 :: "r"(s), "l"(gptr) : "memory");
}
#define CP_COMMIT() asm volatile("cp.async.commit_group;" ::: "memory")
#define CP_WAIT2()  asm volatile("cp.async.wait_group 2;" ::: "memory")
#define CP_WAIT1()  asm volatile("cp.async.wait_group 1;" ::: "memory")
#define CP_WAIT0()  asm volatile("cp.async.wait_group 0;" ::: "memory")

__device__ __forceinline__ void mma16816(float* d, const uint32_t* a,
                                         uint32_t b0, uint32_t b1) {
    asm volatile(
        "mma.sync.aligned.m16n8k16.row.col.f32.bf16.bf16.f32 "
        "{%0,%1,%2,%3}, {%4,%5,%6,%7}, {%8,%9}, {%0,%1,%2,%3};"
        : "+f"(d[0]), "+f"(d[1]), "+f"(d[2]), "+f"(d[3])
        : "r"(a[0]), "r"(a[1]), "r"(a[2]), "r"(a[3]), "r"(b0), "r"(b1));
}
__device__ __forceinline__ void ldmx4(uint32_t* r, uint32_t addr) {
    asm volatile(
        "ldmatrix.sync.aligned.m8n8.x4.shared.b16 {%0,%1,%2,%3}, [%4];"
        : "=r"(r[0]), "=r"(r[1]), "=r"(r[2]), "=r"(r[3]) : "r"(addr));
}

// ---------------------------------------------------------------- kernel 1
// Fused prep: zero output, convert X and W to bf16, init scalars.
__global__ void prep_kernel(const float4* __restrict__ X4,
                            const float4* __restrict__ W4,
                            float4* __restrict__ out) {
    const unsigned int i = blockIdx.x * blockDim.x + threadIdx.x;
    if (i < NROWS) g_best[i] = 0ull;
    if (i == 0) { g_cand_count = 0; g_done = 0u; }
    if (i < OUT_ELEMS / 4) out[i] = make_float4(0.f, 0.f, 0.f, 0.f);
    if (i < (unsigned)(M_TOT * C_ / 4)) {
        float4 v = X4[i];
        __nv_bfloat162 h0 = __floats2bfloat162_rn(v.x, v.y);
        __nv_bfloat162 h1 = __floats2bfloat162_rn(v.z, v.w);
        ((uint2*)g_Xh)[i] = make_uint2(*(uint32_t*)&h0, *(uint32_t*)&h1);
    }
    if (i < (unsigned)(GE_ * C_ / 4)) {
        float4 v = W4[i];
        __nv_bfloat162 h0 = __floats2bfloat162_rn(v.x, v.y);
        __nv_bfloat162 h1 = __floats2bfloat162_rn(v.z, v.w);
        ((uint2*)g_Wh)[i] = make_uint2(*(uint32_t*)&h0, *(uint32_t*)&h1);
    }
}

// ---------------------------------------------------------------- kernel 2
// 128x64 bf16 HMMA GEMM, 128 threads (4 warps of 32m x 64n), 4-stage
// cp.async pipeline, ldmatrix loads. Epilogue: bias + tile max + candidates.
__global__ void __launch_bounds__(128, 3)
gemm_cand_kernel(const float* __restrict__ bias) {
    extern __shared__ __nv_bfloat16 sm[];
    __shared__ float s_wmax[4];
    __shared__ float s_tmax;

    const int tid  = threadIdx.x;
    const int lane = tid & 31;
    const int w    = tid >> 5;        // 0..3, warp covers m rows w*32..w*32+31
    const int r4   = lane >> 2;
    const int c4   = lane & 3;

    const int m0 = blockIdx.x * BM;
    const int n0 = blockIdx.y * BN;

    const int arow = tid >> 2;        // 0..31
    const int gcol = tid & 3;         // 4 x 16B chunks per 64B row

    const uint32_t smBase = smem_u32(sm);
    const uint32_t aAddrBase = smBase +
        (((w * 32 + (lane & 15)) * PITCH + ((lane >> 4) << 3)) << 1);
    const uint32_t bAddrBase = smBase + (A_ELE << 1) +
        ((((lane & 7) + ((lane >> 4) << 3)) * PITCH
          + (((lane >> 3) & 1) << 3)) << 1);

    float acc[2][8][4];
#pragma unroll
    for (int i = 0; i < 2; i++)
#pragma unroll
        for (int j = 0; j < 8; j++)
#pragma unroll
            for (int k = 0; k < 4; k++) acc[i][j][k] = 0.f;

    // prologue: stages 0..2
#pragma unroll
    for (int c = 0; c < 3; c++) {
        const int k0 = c * BK;
        __nv_bfloat16* stg = sm + c * STAGE_ELE;
#pragma unroll
        for (int q = 0; q < 4; q++) {               // A: 128 rows
            const int row = arow + q * 32;
            cp16(stg + row * PITCH + gcol * 8,
                 g_Xh + (size_t)(m0 + row) * C_ + k0 + gcol * 8);
        }
#pragma unroll
        for (int q = 0; q < 2; q++) {               // B: 64 rows
            const int row = arow + q * 32;
            cp16(stg + A_ELE + row * PITCH + gcol * 8,
                 g_Wh + (size_t)(n0 + row) * C_ + k0 + gcol * 8);
        }
        CP_COMMIT();
    }

    for (int it = 0; it < NCHUNK; ++it) {
        if (it < NCHUNK - 2)       CP_WAIT2();
        else if (it == NCHUNK - 2) CP_WAIT1();
        else                       CP_WAIT0();
        __syncthreads();   // publishes chunk `it`; proves it-1 fully consumed

        if (it + 3 < NCHUNK) {
            const int slot = (it + 3) & (NSTAGE - 1);
            const int k0 = (it + 3) * BK;
            __nv_bfloat16* stg = sm + slot * STAGE_ELE;
#pragma unroll
            for (int q = 0; q < 4; q++) {
                const int row = arow + q * 32;
                cp16(stg + row * PITCH + gcol * 8,
                     g_Xh + (size_t)(m0 + row) * C_ + k0 + gcol * 8);
            }
#pragma unroll
            for (int q = 0; q < 2; q++) {
                const int row = arow + q * 32;
                cp16(stg + A_ELE + row * PITCH + gcol * 8,
                     g_Wh + (size_t)(n0 + row) * C_ + k0 + gcol * 8);
            }
            CP_COMMIT();
        }

        const uint32_t stageOff = (uint32_t)(it & (NSTAGE - 1)) * STAGE_BYTES;
        const uint32_t aAddr = aAddrBase + stageOff;
        const uint32_t bAddr = bAddrBase + stageOff;
#pragma unroll
        for (int ks = 0; ks < 2; ++ks) {
            const uint32_t kOffB = (uint32_t)(ks * 16 * 2);
            uint32_t a0[4], a1[4];
            ldmx4(a0, aAddr + kOffB);                      // m16 tile 0
            ldmx4(a1, aAddr + 16 * PITCH * 2 + kOffB);     // m16 tile 1
#pragma unroll
            for (int nt2 = 0; nt2 < 4; ++nt2) {
                uint32_t bb[4];
                ldmx4(bb, bAddr + (uint32_t)(nt2 * 16 * PITCH * 2) + kOffB);
                mma16816(acc[0][2 * nt2],     a0, bb[0], bb[1]);
                mma16816(acc[0][2 * nt2 + 1], a0, bb[2], bb[3]);
                mma16816(acc[1][2 * nt2],     a1, bb[0], bb[1]);
                mma16816(acc[1][2 * nt2 + 1], a1, bb[2], bb[3]);
            }
        }
    }

    // ---------------- epilogue: bias, tile max, candidate push
    float best = -3.4e38f;
    const int mBase = m0 + w * 32;
#pragma unroll
    for (int nt = 0; nt < 8; ++nt) {
        const int nc = n0 + nt * 8 + c4 * 2;
        const float b0 = bias[nc];
        const float b1 = bias[nc + 1];
#pragma unroll
        for (int mt = 0; mt < 2; ++mt) {
            acc[mt][nt][0] += b0;
            acc[mt][nt][1] += b1;
            acc[mt][nt][2] += b0;
            acc[mt][nt][3] += b1;
            best = fmaxf(best,
                   fmaxf(fmaxf(acc[mt][nt][0], acc[mt][nt][1]),
                         fmaxf(acc[mt][nt][2], acc[mt][nt][3])));
        }
    }
#pragma unroll
    for (int o = 16; o; o >>= 1)
        best = fmaxf(best, __shfl_xor_sync(0xFFFFFFFFu, best, o));
    if (lane == 0) s_wmax[w] = best;
    __syncthreads();
    if (tid == 0) {
        float t = s_wmax[0];
#pragma unroll
        for (int i = 1; i < 4; i++) t = fmaxf(t, s_wmax[i]);
        s_tmax = t;
    }
    __syncthreads();
    const float thr = s_tmax - DELTA;

#pragma unroll
    for (int nt = 0; nt < 8; ++nt) {
        const int nc = n0 + nt * 8 + c4 * 2;
#pragma unroll
        for (int mt = 0; mt < 2; ++mt) {
#pragma unroll
            for (int e = 0; e < 4; ++e) {
                if (acc[mt][nt][e] >= thr) {
                    const int mr = mBase + mt * 16 + r4 + (e >= 2 ? 8 : 0);
                    const int n  = nc + (e & 1);
                    const unsigned int packed =
                        (unsigned int)mr * (unsigned)GE_ + (unsigned)n;
                    const int pos = atomicAdd(&g_cand_count, 1);
                    if (pos >= 0 && pos < CAND_CAP) g_cand[pos] = packed;
                }
            }
        }
    }
}

// ---------------------------------------------------------------- kernel 3
// Exact fp32 dot for every candidate + fused scatter (last block).
__global__ void exact_scatter_kernel(const float* __restrict__ X,
                                     const float* __restrict__ W,
                                     const float* __restrict__ bias,
                                     const float* __restrict__ cb,
                                     float* __restrict__ out) {
    __shared__ unsigned int s_last;
    const int lane = threadIdx.x & 31;
    const int wid  = threadIdx.x >> 5;          // 0..7
    int cnt = g_cand_count;
    if (cnt > CAND_CAP) cnt = CAND_CAP;
    for (int ci = blockIdx.x * 8 + wid; ci < cnt; ci += gridDim.x * 8) {
        const unsigned int packed = g_cand[ci];
        if (packed >= (unsigned int)LOGITS_N) continue;
        const unsigned int m = packed / GE_;
        const unsigned int n = packed % GE_;
        const float* xr = X + (size_t)m * C_;
        const float* wr = W + (size_t)n * C_;
        float s = 0.f;
#pragma unroll 8
        for (int j = lane; j < C_; j += 32) s = fmaf(xr[j], wr[j], s);
#pragma unroll
        for (int o = 16; o; o >>= 1) s += __shfl_xor_sync(0xFFFFFFFFu, s, o);
        if (lane == 0) {
            const float ev = s + bias[n];
            const unsigned int r = (m >> 10) & (NROWS - 1);
            const unsigned int idx = (m & 1023u) * (unsigned)GE_ + n;
            const unsigned long long p =
                ((unsigned long long)float_to_ordered(ev) << 32)
                | (unsigned long long)(0xFFFFFFFFu - idx);
            atomicMax(&g_best[r], p);
        }
    }

    // ---- last-block-done: the final block performs the scatter
    __syncthreads();
    if (threadIdx.x == 0) {
        __threadfence();
        const unsigned int prev = atomicAdd(&g_done, 1u);
        s_last = (prev == (unsigned int)gridDim.x - 1u) ? 1u : 0u;
    }
    __syncthreads();
    if (!s_last) return;

    for (int r = 0; r < NROWS; ++r) {
        const unsigned long long p = g_best[r];
        if (p == 0ull) continue;
        const unsigned int idx = 0xFFFFFFFFu - (unsigned int)(p & 0xFFFFFFFFull);
        if (idx >= ROW_SPAN) continue;
        const unsigned long long flat = (unsigned long long)r * ROW_SPAN + idx;
        const unsigned int n   = (unsigned int)(flat / GE_);
        const unsigned int rem = (unsigned int)(flat % GE_);
        const unsigned int g   = rem / E_;
        const size_t oidx = (size_t)n * (G_ * D_) + g * D_ + threadIdx.x;
        if (threadIdx.x < D_ && oidx < (size_t)OUT_ELEMS && rem < GE_)
            out[oidx] = cb[(size_t)rem * D_ + threadIdx.x];
    }
}

// ---------------------------------------------------------------- launch
extern "C" void kernel_launch(void* const* d_in, const int* in_sizes, int n_in,
                              void* d_out, int out_size) {
    const float* X    = (const float*)d_in[0];
    const float* W    = (const float*)d_in[1];
    const float* bias = (const float*)d_in[2];
    const float* cb   = (const float*)d_in[3];
    float* out        = (float*)d_out;

    cudaFuncSetAttribute(gemm_cand_kernel,
                         cudaFuncAttributeMaxDynamicSharedMemorySize, SMEM_BYTES);

    prep_kernel<<<(M_TOT * C_ / 4) / 256, 256>>>(
        (const float4*)X, (const float4*)W, (float4*)out);

    dim3 grid(M_TOT / BM, GE_ / BN);     // 128 x 10 = 1280 CTAs
    gemm_cand_kernel<<<grid, 128, SMEM_BYTES>>>(bias);

    exact_scatter_kernel<<<EXACT_BLOCKS, 256>>>(X, W, bias, cb, out);
}

// round 14
// speedup vs baseline: 1.1235x; 1.1235x over previous
#include <cuda_runtime.h>
#include <cuda_bf16.h>
#include <cstdint>

// ---------------------------------------------------------------- constants
#define B_      8
#define T_      2048
#define C_      1024
#define G_      2
#define E_      320
#define GE_     640
#define D_      256
#define M_TOT   16384
#define NROWS   16
#define ROW_SPAN 655360u
#define OUT_ELEMS (B_*T_*G_*D_)          // 8,388,608
#define LOGITS_N ((size_t)M_TOT * GE_)   // 10,485,760

#define BM 128
#define BN 64
#define BK 32
#define PITCH 40            // bf16 per smem row (32 data + 8 pad) -> 80B
#define NCHUNK (C_/BK)      // 32
#define NSTAGE 4
#define A_ELE (BM * PITCH)               // 5120 bf16
#define B_ELE (BN * PITCH)               // 2560 bf16
#define STAGE_ELE (A_ELE + B_ELE)        // 7680
#define STAGE_BYTES (STAGE_ELE * 2)      // 15360
#define SMEM_BYTES (NSTAGE * STAGE_BYTES)  // 61440 -> 3 CTAs/SM
#define DELTA 4.0f
#define CAND_CAP 65536

// ---------------------------------------------------------------- scratch
__device__ unsigned long long g_best[NROWS];
__device__ int                g_cand_count;
__device__ unsigned int       g_cand[CAND_CAP];
__device__ __align__(16) __nv_bfloat16 g_Xh[(size_t)M_TOT * C_];
__device__ __align__(16) __nv_bfloat16 g_Wh[(size_t)GE_ * C_];

// ---------------------------------------------------------------- helpers
__device__ __forceinline__ unsigned int float_to_ordered(float f) {
    unsigned int u = __float_as_uint(f);
    return (u & 0x80000000u) ? ~u : (u | 0x80000000u);
}
__device__ __forceinline__ uint32_t smem_u32(const void* p) {
    uint32_t a;
    asm("{ .reg .u64 t; cvta.to.shared.u64 t, %1; cvt.u32.u64 %0, t; }"
        : "=r"(a) : "l"(p));
    return a;
}
__device__ __forceinline__ void cp16(void* sptr, const void* gptr) {
    uint32_t s = smem_u32(sptr);
    asm volatile("cp.async.cg.shared.global [%0], [%1], 16;"
                 :: "r"(s), "l"(gptr) : "memory");
}
#define CP_COMMIT() asm volatile("cp.async.commit_group;" ::: "memory")
#define CP_WAIT2()  asm volatile("cp.async.wait_group 2;" ::: "memory")
#define CP_WAIT1()  asm volatile("cp.async.wait_group 1;" ::: "memory")
#define CP_WAIT0()  asm volatile("cp.async.wait_group 0;" ::: "memory")

__device__ __forceinline__ float4 ldg_cs4(const float4* p) {
    float4 v;
    asm volatile("ld.global.cs.v4.f32 {%0,%1,%2,%3}, [%4];"
                 : "=f"(v.x), "=f"(v.y), "=f"(v.z), "=f"(v.w) : "l"(p));
    return v;
}
__device__ __forceinline__ void stg_cs4(float4* p, float4 v) {
    asm volatile("st.global.cs.v4.f32 [%0], {%1,%2,%3,%4};"
                 :: "l"(p), "f"(v.x), "f"(v.y), "f"(v.z), "f"(v.w) : "memory");
}

__device__ __forceinline__ void mma16816(float* d, const uint32_t* a,
                                         uint32_t b0, uint32_t b1) {
    asm volatile(
        "mma.sync.aligned.m16n8k16.row.col.f32.bf16.bf16.f32 "
        "{%0,%1,%2,%3}, {%4,%5,%6,%7}, {%8,%9}, {%0,%1,%2,%3};"
        : "+f"(d[0]), "+f"(d[1]), "+f"(d[2]), "+f"(d[3])
        : "r"(a[0]), "r"(a[1]), "r"(a[2]), "r"(a[3]), "r"(b0), "r"(b1));
}
__device__ __forceinline__ void ldmx4(uint32_t* r, uint32_t addr) {
    asm volatile(
        "ldmatrix.sync.aligned.m8n8.x4.shared.b16 {%0,%1,%2,%3}, [%4];"
        : "=r"(r[0]), "=r"(r[1]), "=r"(r[2]), "=r"(r[3]) : "r"(addr));
}
__device__ __forceinline__ uint2 cvt_pack4(float4 v) {
    __nv_bfloat162 h0 = __floats2bfloat162_rn(v.x, v.y);
    __nv_bfloat162 h1 = __floats2bfloat162_rn(v.z, v.w);
    return make_uint2(*(uint32_t*)&h0, *(uint32_t*)&h1);
}

// ---------------------------------------------------------------- kernel 1
// Prep: convert X (2 float4/thread, streaming loads), convert W, zero out
// (streaming stores), init scalars. 2,097,152 threads.
__global__ void prep_kernel(const float4* __restrict__ X4,
                            const float4* __restrict__ W4,
                            float4* __restrict__ out) {
    const unsigned int i = blockIdx.x * blockDim.x + threadIdx.x; // < 2097152
    const unsigned int NT = (unsigned)(M_TOT * C_ / 8);           // 2097152

    if (i < NROWS) g_best[i] = 0ull;
    if (i == 0) g_cand_count = 0;

    // X: 4,194,304 float4 -> 2 per thread (independent loads, MLP=2)
    const float4 v0 = ldg_cs4(X4 + i);
    const float4 v1 = ldg_cs4(X4 + i + NT);
    ((uint2*)g_Xh)[i]      = cvt_pack4(v0);
    ((uint2*)g_Xh)[i + NT] = cvt_pack4(v1);

    // out: 2,097,152 float4 -> exactly 1 per thread, streaming store
    stg_cs4(out + i, make_float4(0.f, 0.f, 0.f, 0.f));

    // W: 163,840 float4
    if (i < (unsigned)(GE_ * C_ / 4)) {
        const float4 w = ldg_cs4(W4 + i);
        ((uint2*)g_Wh)[i] = cvt_pack4(w);
    }
}

// ---------------------------------------------------------------- kernel 2
// 128x64 bf16 HMMA GEMM, 128 threads (4 warps of 32m x 64n), 4-stage
// cp.async pipeline, ldmatrix loads. Epilogue: bias + tile max + candidates.
__global__ void __launch_bounds__(128, 3)
gemm_cand_kernel(const float* __restrict__ bias) {
    extern __shared__ __nv_bfloat16 sm[];
    __shared__ float s_wmax[4];
    __shared__ float s_tmax;

    const int tid  = threadIdx.x;
    const int lane = tid & 31;
    const int w    = tid >> 5;        // 0..3, warp covers m rows w*32..w*32+31
    const int r4   = lane >> 2;
    const int c4   = lane & 3;

    const int m0 = blockIdx.x * BM;
    const int n0 = blockIdx.y * BN;

    const int arow = tid >> 2;        // 0..31
    const int gcol = tid & 3;         // 4 x 16B chunks per 64B row

    const uint32_t smBase = smem_u32(sm);
    const uint32_t aAddrBase = smBase +
        (((w * 32 + (lane & 15)) * PITCH + ((lane >> 4) << 3)) << 1);
    const uint32_t bAddrBase = smBase + (A_ELE << 1) +
        ((((lane & 7) + ((lane >> 4) << 3)) * PITCH
          + (((lane >> 3) & 1) << 3)) << 1);

    float acc[2][8][4];
#pragma unroll
    for (int i = 0; i < 2; i++)
#pragma unroll
        for (int j = 0; j < 8; j++)
#pragma unroll
            for (int k = 0; k < 4; k++) acc[i][j][k] = 0.f;

    // prologue: stages 0..2
#pragma unroll
    for (int c = 0; c < 3; c++) {
        const int k0 = c * BK;
        __nv_bfloat16* stg = sm + c * STAGE_ELE;
#pragma unroll
        for (int q = 0; q < 4; q++) {               // A: 128 rows
            const int row = arow + q * 32;
            cp16(stg + row * PITCH + gcol * 8,
                 g_Xh + (size_t)(m0 + row) * C_ + k0 + gcol * 8);
        }
#pragma unroll
        for (int q = 0; q < 2; q++) {               // B: 64 rows
            const int row = arow + q * 32;
            cp16(stg + A_ELE + row * PITCH + gcol * 8,
                 g_Wh + (size_t)(n0 + row) * C_ + k0 + gcol * 8);
        }
        CP_COMMIT();
    }

    for (int it = 0; it < NCHUNK; ++it) {
        if (it < NCHUNK - 2)       CP_WAIT2();
        else if (it == NCHUNK - 2) CP_WAIT1();
        else                       CP_WAIT0();
        __syncthreads();   // publishes chunk `it`; proves it-1 fully consumed

        if (it + 3 < NCHUNK) {
            const int slot = (it + 3) & (NSTAGE - 1);
            const int k0 = (it + 3) * BK;
            __nv_bfloat16* stg = sm + slot * STAGE_ELE;
#pragma unroll
            for (int q = 0; q < 4; q++) {
                const int row = arow + q * 32;
                cp16(stg + row * PITCH + gcol * 8,
                     g_Xh + (size_t)(m0 + row) * C_ + k0 + gcol * 8);
            }
#pragma unroll
            for (int q = 0; q < 2; q++) {
                const int row = arow + q * 32;
                cp16(stg + A_ELE + row * PITCH + gcol * 8,
                     g_Wh + (size_t)(n0 + row) * C_ + k0 + gcol * 8);
            }
            CP_COMMIT();
        }

        const uint32_t stageOff = (uint32_t)(it & (NSTAGE - 1)) * STAGE_BYTES;
        const uint32_t aAddr = aAddrBase + stageOff;
        const uint32_t bAddr = bAddrBase + stageOff;
#pragma unroll
        for (int ks = 0; ks < 2; ++ks) {
            const uint32_t kOffB = (uint32_t)(ks * 16 * 2);
            uint32_t a0[4], a1[4];
            ldmx4(a0, aAddr + kOffB);                      // m16 tile 0
            ldmx4(a1, aAddr + 16 * PITCH * 2 + kOffB);     // m16 tile 1
#pragma unroll
            for (int nt2 = 0; nt2 < 4; ++nt2) {
                uint32_t bb[4];
                ldmx4(bb, bAddr + (uint32_t)(nt2 * 16 * PITCH * 2) + kOffB);
                mma16816(acc[0][2 * nt2],     a0, bb[0], bb[1]);
                mma16816(acc[0][2 * nt2 + 1], a0, bb[2], bb[3]);
                mma16816(acc[1][2 * nt2],     a1, bb[0], bb[1]);
                mma16816(acc[1][2 * nt2 + 1], a1, bb[2], bb[3]);
            }
        }
    }

    // ---------------- epilogue: bias, tile max, candidate push
    float best = -3.4e38f;
    const int mBase = m0 + w * 32;
#pragma unroll
    for (int nt = 0; nt < 8; ++nt) {
        const int nc = n0 + nt * 8 + c4 * 2;
        const float b0 = bias[nc];
        const float b1 = bias[nc + 1];
#pragma unroll
        for (int mt = 0; mt < 2; ++mt) {
            acc[mt][nt][0] += b0;
            acc[mt][nt][1] += b1;
            acc[mt][nt][2] += b0;
            acc[mt][nt][3] += b1;
            best = fmaxf(best,
                   fmaxf(fmaxf(acc[mt][nt][0], acc[mt][nt][1]),
                         fmaxf(acc[mt][nt][2], acc[mt][nt][3])));
        }
    }
#pragma unroll
    for (int o = 16; o; o >>= 1)
        best = fmaxf(best, __shfl_xor_sync(0xFFFFFFFFu, best, o));
    if (lane == 0) s_wmax[w] = best;
    __syncthreads();
    if (tid == 0) {
        float t = s_wmax[0];
#pragma unroll
        for (int i = 1; i < 4; i++) t = fmaxf(t, s_wmax[i]);
        s_tmax = t;
    }
    __syncthreads();
    const float thr = s_tmax - DELTA;

#pragma unroll
    for (int nt = 0; nt < 8; ++nt) {
        const int nc = n0 + nt * 8 + c4 * 2;
#pragma unroll
        for (int mt = 0; mt < 2; ++mt) {
#pragma unroll
            for (int e = 0; e < 4; ++e) {
                if (acc[mt][nt][e] >= thr) {
                    const int mr = mBase + mt * 16 + r4 + (e >= 2 ? 8 : 0);
                    const int n  = nc + (e & 1);
                    const unsigned int packed =
                        (unsigned int)mr * (unsigned)GE_ + (unsigned)n;
                    const int pos = atomicAdd(&g_cand_count, 1);
                    if (pos >= 0 && pos < CAND_CAP) g_cand[pos] = packed;
                }
            }
        }
    }
}

// ---------------------------------------------------------------- kernel 3
__global__ void exact_kernel(const float* __restrict__ X,
                             const float* __restrict__ W,
                             const float* __restrict__ bias) {
    const int lane = threadIdx.x & 31;
    const int wid  = threadIdx.x >> 5;          // 0..7
    int cnt = g_cand_count;
    if (cnt > CAND_CAP) cnt = CAND_CAP;
    for (int ci = blockIdx.x * 8 + wid; ci < cnt; ci += gridDim.x * 8) {
        const unsigned int packed = g_cand[ci];
        if (packed >= (unsigned int)LOGITS_N) continue;
        const unsigned int m = packed / GE_;
        const unsigned int n = packed % GE_;
        const float* xr = X + (size_t)m * C_;
        const float* wr = W + (size_t)n * C_;
        float s = 0.f;
#pragma unroll 8
        for (int j = lane; j < C_; j += 32) s = fmaf(xr[j], wr[j], s);
#pragma unroll
        for (int o = 16; o; o >>= 1) s += __shfl_xor_sync(0xFFFFFFFFu, s, o);
        if (lane == 0) {
            const float ev = s + bias[n];
            const unsigned int r = (m >> 10) & (NROWS - 1);
            const unsigned int idx = (m & 1023u) * (unsigned)GE_ + n;
            const unsigned long long p =
                ((unsigned long long)float_to_ordered(ev) << 32)
                | (unsigned long long)(0xFFFFFFFFu - idx);
            atomicMax(&g_best[r], p);
        }
    }
}

// ---------------------------------------------------------------- kernel 4
__global__ void scatter_kernel(const float* __restrict__ cb,
                               float* __restrict__ out) {
    const int r = blockIdx.x;
    if (r >= NROWS) return;
    const unsigned long long p = g_best[r];
    if (p == 0ull) return;
    const unsigned int idx = 0xFFFFFFFFu - (unsigned int)(p & 0xFFFFFFFFull);
    if (idx >= ROW_SPAN) return;
    const unsigned long long flat = (unsigned long long)r * ROW_SPAN + idx;
    const unsigned int n   = (unsigned int)(flat / GE_);
    const unsigned int rem = (unsigned int)(flat % GE_);
    const unsigned int g   = rem / E_;
    const size_t oidx = (size_t)n * (G_ * D_) + g * D_ + threadIdx.x;
    if (oidx < (size_t)OUT_ELEMS && rem < GE_)
        out[oidx] = cb[(size_t)rem * D_ + threadIdx.x];
}

// ---------------------------------------------------------------- launch
extern "C" void kernel_launch(void* const* d_in, const int* in_sizes, int n_in,
                              void* d_out, int out_size) {
    const float* X    = (const float*)d_in[0];
    const float* W    = (const float*)d_in[1];
    const float* bias = (const float*)d_in[2];
    const float* cb   = (const float*)d_in[3];
    float* out        = (float*)d_out;

    cudaFuncSetAttribute(gemm_cand_kernel,
                         cudaFuncAttributeMaxDynamicSharedMemorySize, SMEM_BYTES);

    prep_kernel<<<(M_TOT * C_ / 8) / 256, 256>>>(
        (const float4*)X, (const float4*)W, (float4*)out);

    dim3 grid(M_TOT / BM, GE_ / BN);     // 128 x 10 = 1280 CTAs
    gemm_cand_kernel<<<grid, 128, SMEM_BYTES>>>(bias);

    exact_kernel<<<256, 256>>>(X, W, bias);
    scatter_kernel<<<NROWS, D_>>>(cb, out);
}

// round 15
// speedup vs baseline: 1.1754x; 1.0462x over previous
#include <cuda_runtime.h>
#include <cuda_bf16.h>
#include <cstdint>

// ---------------------------------------------------------------- constants
#define B_      8
#define T_      2048
#define C_      1024
#define G_      2
#define E_      320
#define GE_     640
#define D_      256
#define M_TOT   16384
#define NROWS   16
#define ROW_SPAN 655360u
#define OUT_ELEMS (B_*T_*G_*D_)          // 8,388,608
#define LOGITS_N ((size_t)M_TOT * GE_)   // 10,485,760

#define BM 128
#define BN 64
#define BK 32
#define PITCH 40            // bf16 per smem row (32 data + 8 pad) -> 80B
#define NCHUNK (C_/BK)      // 32
#define NSTAGE 4
#define A_ELE (BM * PITCH)               // 5120 bf16
#define B_ELE (BN * PITCH)               // 2560 bf16
#define STAGE_ELE (A_ELE + B_ELE)        // 7680
#define STAGE_BYTES (STAGE_ELE * 2)      // 15360
#define SMEM_BYTES (NSTAGE * STAGE_BYTES)  // 61440 -> 3 CTAs/SM
#define DELTA 4.0f
#define CAND_CAP 65536

// ---------------------------------------------------------------- scratch
__device__ unsigned long long g_best[NROWS];
__device__ int                g_cand_count;
__device__ unsigned int       g_cand[CAND_CAP];
__device__ __align__(16) __nv_bfloat16 g_Xh[(size_t)M_TOT * C_];
__device__ __align__(16) __nv_bfloat16 g_Wh[(size_t)GE_ * C_];

// ---------------------------------------------------------------- helpers
__device__ __forceinline__ unsigned int float_to_ordered(float f) {
    unsigned int u = __float_as_uint(f);
    return (u & 0x80000000u) ? ~u : (u | 0x80000000u);
}
__device__ __forceinline__ uint32_t smem_u32(const void* p) {
    uint32_t a;
    asm("{ .reg .u64 t; cvta.to.shared.u64 t, %1; cvt.u32.u64 %0, t; }"
        : "=r"(a) : "l"(p));
    return a;
}
__device__ __forceinline__ void cp16(void* sptr, const void* gptr) {
    uint32_t s = smem_u32(sptr);
    asm volatile("cp.async.cg.shared.global [%0], [%1], 16;"
                 :: "r"(s), "l"(gptr) : "memory");
}
#define CP_COMMIT() asm volatile("cp.async.commit_group;" ::: "memory")
#define CP_WAIT2()  asm volatile("cp.async.wait_group 2;" ::: "memory")
#define CP_WAIT1()  asm volatile("cp.async.wait_group 1;" ::: "memory")
#define CP_WAIT0()  asm volatile("cp.async.wait_group 0;" ::: "memory")

__device__ __forceinline__ float4 ldg_cs4(const float4* p) {
    float4 v;
    asm volatile("ld.global.cs.v4.f32 {%0,%1,%2,%3}, [%4];"
                 : "=f"(v.x), "=f"(v.y), "=f"(v.z), "=f"(v.w) : "l"(p));
    return v;
}
__device__ __forceinline__ void stg_cs4(float4* p, float4 v) {
    asm volatile("st.global.cs.v4.f32 [%0], {%1,%2,%3,%4};"
                 :: "l"(p), "f"(v.x), "f"(v.y), "f"(v.z), "f"(v.w) : "memory");
}

__device__ __forceinline__ void mma16816(float* d, const uint32_t* a,
                                         uint32_t b0, uint32_t b1) {
    asm volatile(
        "mma.sync.aligned.m16n8k16.row.col.f32.bf16.bf16.f32 "
        "{%0,%1,%2,%3}, {%4,%5,%6,%7}, {%8,%9}, {%0,%1,%2,%3};"
        : "+f"(d[0]), "+f"(d[1]), "+f"(d[2]), "+f"(d[3])
        : "r"(a[0]), "r"(a[1]), "r"(a[2]), "r"(a[3]), "r"(b0), "r"(b1));
}
__device__ __forceinline__ void ldmx4(uint32_t* r, uint32_t addr) {
    asm volatile(
        "ldmatrix.sync.aligned.m8n8.x4.shared.b16 {%0,%1,%2,%3}, [%4];"
        : "=r"(r[0]), "=r"(r[1]), "=r"(r[2]), "=r"(r[3]) : "r"(addr));
}
__device__ __forceinline__ uint2 cvt_pack4(float4 v) {
    __nv_bfloat162 h0 = __floats2bfloat162_rn(v.x, v.y);
    __nv_bfloat162 h1 = __floats2bfloat162_rn(v.z, v.w);
    return make_uint2(*(uint32_t*)&h0, *(uint32_t*)&h1);
}

// ---------------------------------------------------------------- kernel 1
// Prep: convert X (2 float4/thread, streaming loads), convert W, zero out
// (streaming stores), init scalars. 2,097,152 threads.
__global__ void prep_kernel(const float4* __restrict__ X4,
                            const float4* __restrict__ W4,
                            float4* __restrict__ out) {
    const unsigned int i = blockIdx.x * blockDim.x + threadIdx.x; // < 2097152
    const unsigned int NT = (unsigned)(M_TOT * C_ / 8);           // 2097152

    if (i < NROWS) g_best[i] = 0ull;
    if (i == 0) g_cand_count = 0;

    const float4 v0 = ldg_cs4(X4 + i);
    const float4 v1 = ldg_cs4(X4 + i + NT);
    ((uint2*)g_Xh)[i]      = cvt_pack4(v0);
    ((uint2*)g_Xh)[i + NT] = cvt_pack4(v1);

    stg_cs4(out + i, make_float4(0.f, 0.f, 0.f, 0.f));

    if (i < (unsigned)(GE_ * C_ / 4)) {
        const float4 w = ldg_cs4(W4 + i);
        ((uint2*)g_Wh)[i] = cvt_pack4(w);
    }
}

// ---------------------------------------------------------------- kernel 2
// 128x64 bf16 HMMA GEMM, 128 threads (4 warps of 32m x 64n), 4-stage
// cp.async pipeline. Per chunk: ALL 12 ldmatrix first, then a burst of
// 64 back-to-back HMMAs (no ldsm->mma serialization inside the burst).
__global__ void __launch_bounds__(128, 3)
gemm_cand_kernel(const float* __restrict__ bias) {
    extern __shared__ __nv_bfloat16 sm[];
    __shared__ float s_wmax[4];
    __shared__ float s_tmax;

    const int tid  = threadIdx.x;
    const int lane = tid & 31;
    const int w    = tid >> 5;        // 0..3, warp covers m rows w*32..w*32+31
    const int r4   = lane >> 2;
    const int c4   = lane & 3;

    const int m0 = blockIdx.x * BM;
    const int n0 = blockIdx.y * BN;

    const int arow = tid >> 2;        // 0..31
    const int gcol = tid & 3;         // 4 x 16B chunks per 64B row

    const uint32_t smBase = smem_u32(sm);
    const uint32_t aAddrBase = smBase +
        (((w * 32 + (lane & 15)) * PITCH + ((lane >> 4) << 3)) << 1);
    const uint32_t bAddrBase = smBase + (A_ELE << 1) +
        ((((lane & 7) + ((lane >> 4) << 3)) * PITCH
          + (((lane >> 3) & 1) << 3)) << 1);

    float acc[2][8][4];
#pragma unroll
    for (int i = 0; i < 2; i++)
#pragma unroll
        for (int j = 0; j < 8; j++)
#pragma unroll
            for (int k = 0; k < 4; k++) acc[i][j][k] = 0.f;

    // prologue: stages 0..2
#pragma unroll
    for (int c = 0; c < 3; c++) {
        const int k0 = c * BK;
        __nv_bfloat16* stg = sm + c * STAGE_ELE;
#pragma unroll
        for (int q = 0; q < 4; q++) {               // A: 128 rows
            const int row = arow + q * 32;
            cp16(stg + row * PITCH + gcol * 8,
                 g_Xh + (size_t)(m0 + row) * C_ + k0 + gcol * 8);
        }
#pragma unroll
        for (int q = 0; q < 2; q++) {               // B: 64 rows
            const int row = arow + q * 32;
            cp16(stg + A_ELE + row * PITCH + gcol * 8,
                 g_Wh + (size_t)(n0 + row) * C_ + k0 + gcol * 8);
        }
        CP_COMMIT();
    }

    for (int it = 0; it < NCHUNK; ++it) {
        if (it < NCHUNK - 2)       CP_WAIT2();
        else if (it == NCHUNK - 2) CP_WAIT1();
        else                       CP_WAIT0();
        __syncthreads();   // publishes chunk `it`; proves it-1 fully consumed

        if (it + 3 < NCHUNK) {
            const int slot = (it + 3) & (NSTAGE - 1);
            const int k0 = (it + 3) * BK;
            __nv_bfloat16* stg = sm + slot * STAGE_ELE;
#pragma unroll
            for (int q = 0; q < 4; q++) {
                const int row = arow + q * 32;
                cp16(stg + row * PITCH + gcol * 8,
                     g_Xh + (size_t)(m0 + row) * C_ + k0 + gcol * 8);
            }
#pragma unroll
            for (int q = 0; q < 2; q++) {
                const int row = arow + q * 32;
                cp16(stg + A_ELE + row * PITCH + gcol * 8,
                     g_Wh + (size_t)(n0 + row) * C_ + k0 + gcol * 8);
            }
            CP_COMMIT();
        }

        const uint32_t stageOff = (uint32_t)(it & (NSTAGE - 1)) * STAGE_BYTES;
        const uint32_t aAddr = aAddrBase + stageOff;
        const uint32_t bAddr = bAddrBase + stageOff;

        // ---- phase 1: ALL fragment loads (12 ldmatrix.x4)
        uint32_t af[2][2][4];   // [ks][mt]
        uint32_t bf[2][4][4];   // [ks][nt2]
#pragma unroll
        for (int ks = 0; ks < 2; ++ks) {
            const uint32_t kOffB = (uint32_t)(ks * 16 * 2);
            ldmx4(af[ks][0], aAddr + kOffB);
            ldmx4(af[ks][1], aAddr + 16 * PITCH * 2 + kOffB);
#pragma unroll
            for (int nt2 = 0; nt2 < 4; ++nt2)
                ldmx4(bf[ks][nt2], bAddr + (uint32_t)(nt2 * 16 * PITCH * 2) + kOffB);
        }
        // ---- phase 2: 64 back-to-back HMMAs
#pragma unroll
        for (int ks = 0; ks < 2; ++ks) {
#pragma unroll
            for (int nt2 = 0; nt2 < 4; ++nt2) {
                mma16816(acc[0][2 * nt2],     af[ks][0], bf[ks][nt2][0], bf[ks][nt2][1]);
                mma16816(acc[0][2 * nt2 + 1], af[ks][0], bf[ks][nt2][2], bf[ks][nt2][3]);
                mma16816(acc[1][2 * nt2],     af[ks][1], bf[ks][nt2][0], bf[ks][nt2][1]);
                mma16816(acc[1][2 * nt2 + 1], af[ks][1], bf[ks][nt2][2], bf[ks][nt2][3]);
            }
        }
    }

    // ---------------- epilogue: bias, tile max, candidate push
    float best = -3.4e38f;
    const int mBase = m0 + w * 32;
#pragma unroll
    for (int nt = 0; nt < 8; ++nt) {
        const int nc = n0 + nt * 8 + c4 * 2;
        const float b0 = bias[nc];
        const float b1 = bias[nc + 1];
#pragma unroll
        for (int mt = 0; mt < 2; ++mt) {
            acc[mt][nt][0] += b0;
            acc[mt][nt][1] += b1;
            acc[mt][nt][2] += b0;
            acc[mt][nt][3] += b1;
            best = fmaxf(best,
                   fmaxf(fmaxf(acc[mt][nt][0], acc[mt][nt][1]),
                         fmaxf(acc[mt][nt][2], acc[mt][nt][3])));
        }
    }
#pragma unroll
    for (int o = 16; o; o >>= 1)
        best = fmaxf(best, __shfl_xor_sync(0xFFFFFFFFu, best, o));
    if (lane == 0) s_wmax[w] = best;
    __syncthreads();
    if (tid == 0) {
        float t = s_wmax[0];
#pragma unroll
        for (int i = 1; i < 4; i++) t = fmaxf(t, s_wmax[i]);
        s_tmax = t;
    }
    __syncthreads();
    const float thr = s_tmax - DELTA;

#pragma unroll
    for (int nt = 0; nt < 8; ++nt) {
        const int nc = n0 + nt * 8 + c4 * 2;
#pragma unroll
        for (int mt = 0; mt < 2; ++mt) {
#pragma unroll
            for (int e = 0; e < 4; ++e) {
                if (acc[mt][nt][e] >= thr) {
                    const int mr = mBase + mt * 16 + r4 + (e >= 2 ? 8 : 0);
                    const int n  = nc + (e & 1);
                    const unsigned int packed =
                        (unsigned int)mr * (unsigned)GE_ + (unsigned)n;
                    const int pos = atomicAdd(&g_cand_count, 1);
                    if (pos >= 0 && pos < CAND_CAP) g_cand[pos] = packed;
                }
            }
        }
    }
}

// ---------------------------------------------------------------- kernel 3
__global__ void exact_kernel(const float* __restrict__ X,
                             const float* __restrict__ W,
                             const float* __restrict__ bias) {
    const int lane = threadIdx.x & 31;
    const int wid  = threadIdx.x >> 5;          // 0..7
    int cnt = g_cand_count;
    if (cnt > CAND_CAP) cnt = CAND_CAP;
    for (int ci = blockIdx.x * 8 + wid; ci < cnt; ci += gridDim.x * 8) {
        const unsigned int packed = g_cand[ci];
        if (packed >= (unsigned int)LOGITS_N) continue;
        const unsigned int m = packed / GE_;
        const unsigned int n = packed % GE_;
        const float* xr = X + (size_t)m * C_;
        const float* wr = W + (size_t)n * C_;
        float s = 0.f;
#pragma unroll 8
        for (int j = lane; j < C_; j += 32) s = fmaf(xr[j], wr[j], s);
#pragma unroll
        for (int o = 16; o; o >>= 1) s += __shfl_xor_sync(0xFFFFFFFFu, s, o);
        if (lane == 0) {
            const float ev = s + bias[n];
            const unsigned int r = (m >> 10) & (NROWS - 1);
            const unsigned int idx = (m & 1023u) * (unsigned)GE_ + n;
            const unsigned long long p =
                ((unsigned long long)float_to_ordered(ev) << 32)
                | (unsigned long long)(0xFFFFFFFFu - idx);
            atomicMax(&g_best[r], p);
        }
    }
}

// ---------------------------------------------------------------- kernel 4
__global__ void scatter_kernel(const float* __restrict__ cb,
                               float* __restrict__ out) {
    const int r = blockIdx.x;
    if (r >= NROWS) return;
    const unsigned long long p = g_best[r];
    if (p == 0ull) return;
    const unsigned int idx = 0xFFFFFFFFu - (unsigned int)(p & 0xFFFFFFFFull);
    if (idx >= ROW_SPAN) return;
    const unsigned long long flat = (unsigned long long)r * ROW_SPAN + idx;
    const unsigned int n   = (unsigned int)(flat / GE_);
    const unsigned int rem = (unsigned int)(flat % GE_);
    const unsigned int g   = rem / E_;
    const size_t oidx = (size_t)n * (G_ * D_) + g * D_ + threadIdx.x;
    if (oidx < (size_t)OUT_ELEMS && rem < GE_)
        out[oidx] = cb[(size_t)rem * D_ + threadIdx.x];
}

// ---------------------------------------------------------------- launch
extern "C" void kernel_launch(void* const* d_in, const int* in_sizes, int n_in,
                              void* d_out, int out_size) {
    const float* X    = (const float*)d_in[0];
    const float* W    = (const float*)d_in[1];
    const float* bias = (const float*)d_in[2];
    const float* cb   = (const float*)d_in[3];
    float* out        = (float*)d_out;

    cudaFuncSetAttribute(gemm_cand_kernel,
                         cudaFuncAttributeMaxDynamicSharedMemorySize, SMEM_BYTES);

    prep_kernel<<<(M_TOT * C_ / 8) / 256, 256>>>(
        (const float4*)X, (const float4*)W, (float4*)out);

    dim3 grid(M_TOT / BM, GE_ / BN);     // 128 x 10 = 1280 CTAs
    gemm_cand_kernel<<<grid, 128, SMEM_BYTES>>>(bias);

    exact_kernel<<<256, 256>>>(X, W, bias);
    scatter_kernel<<<NROWS, D_>>>(cb, out);
}